// round 16
// baseline (speedup 1.0000x reference)
#include <cuda_runtime.h>
#include <cuda_fp16.h>
#include <cstdint>
#include <math.h>

#define BATCH 8
#define SLEN 1024
#define EMB 768
#define NH 12
#define HD 64
#define MROWS (BATCH*SLEN)

__device__ float g_gate[BATCH*NH*SLEN];
__device__ float g_rbt[NH*2048];
__device__ __half g_Xh[MROWS*EMB];
__device__ __half g_AO[MROWS*EMB];
__device__ __half g_WTh[4*EMB*EMB];
__device__ __half g_Qh[BATCH*NH*SLEN*HD];
__device__ __half g_Kh[BATCH*NH*SLEN*HD];
__device__ __half g_Vh[BATCH*NH*SLEN*HD];

__device__ __forceinline__ uint32_t smem_u32(const void* p) {
    uint32_t a;
    asm("{.reg .u64 t; cvta.to.shared.u64 t,%1; cvt.u32.u64 %0,t;}" : "=r"(a) : "l"(p));
    return a;
}
__device__ __forceinline__ void ldm4(uint32_t* r, uint32_t addr) {
    asm volatile("ldmatrix.sync.aligned.m8n8.x4.shared.b16 {%0,%1,%2,%3}, [%4];"
        : "=r"(r[0]),"=r"(r[1]),"=r"(r[2]),"=r"(r[3]) : "r"(addr));
}
__device__ __forceinline__ void ldm4t(uint32_t* r, uint32_t addr) {
    asm volatile("ldmatrix.sync.aligned.m8n8.x4.trans.shared.b16 {%0,%1,%2,%3}, [%4];"
        : "=r"(r[0]),"=r"(r[1]),"=r"(r[2]),"=r"(r[3]) : "r"(addr));
}
__device__ __forceinline__ void mma16816(float* c, const uint32_t* a, const uint32_t* b) {
    asm volatile("mma.sync.aligned.m16n8k16.row.col.f32.f16.f16.f32 "
        "{%0,%1,%2,%3}, {%4,%5,%6,%7}, {%8,%9}, {%0,%1,%2,%3};"
        : "+f"(c[0]),"+f"(c[1]),"+f"(c[2]),"+f"(c[3])
        : "r"(a[0]),"r"(a[1]),"r"(a[2]),"r"(a[3]), "r"(b[0]),"r"(b[1]));
}
__device__ __forceinline__ uint32_t packh2(float hi, float lo) {
    uint32_t r;
    asm("cvt.rn.f16x2.f32 %0, %1, %2;" : "=r"(r) : "f"(hi), "f"(lo));
    return r;
}
__device__ __forceinline__ void cpa16(uint32_t saddr, const void* g) {
    asm volatile("cp.async.cg.shared.global [%0], [%1], 16;" :: "r"(saddr), "l"(g));
}
#define CP_COMMIT() asm volatile("cp.async.commit_group;" ::: "memory")
#define CP_WAIT0()  asm volatile("cp.async.wait_group 0;" ::: "memory")
#define CP_WAIT1()  asm volatile("cp.async.wait_group 1;" ::: "memory")

// e^x for x in [-40, 0], FMA-pipe only
__device__ __forceinline__ float fexp(float x) {
    float y = x * 1.4426950408889634f;
    float t = y + 12582912.f;
    int  i = __float_as_int(t) << 23;
    float f = y - (t - 12582912.f);
    float p = 0.0013333558f;
    p = fmaf(p, f, 0.0096181291f);
    p = fmaf(p, f, 0.0555041087f);
    p = fmaf(p, f, 0.2402265069f);
    p = fmaf(p, f, 0.6931471806f);
    p = fmaf(p, f, 1.0f);
    return __int_as_float(__float_as_int(p) + i);
}

// ---- rel-bias table ----
__global__ __launch_bounds__(256) void rb_kernel(const float* __restrict__ rel_embed) {
    int h = blockIdx.y;
    int idx = blockIdx.x*256 + threadIdx.x;
    int rp = idx - 1023;
    int base = (rp > 0) ? 16 : 0, a = abs(rp), add;
    if(a<8)add=a; else if(a<12)add=8; else if(a<16)add=9; else if(a<23)add=10;
    else if(a<32)add=11; else if(a<46)add=12; else if(a<64)add=13; else if(a<91)add=14; else add=15;
    float v = (idx < 2047) ? rel_embed[(base+add)*NH + h] : 0.f;
    g_rbt[h*2048 + idx] = v;
}

// ---- fused: X -> fp16 + gate ----
__global__ __launch_bounds__(384) void prep_x_kernel(
    const float* __restrict__ query, const float* __restrict__ gW,
    const float* __restrict__ gb, const float* __restrict__ gc)
{
    __shared__ float xrow[EMB];
    __shared__ float sw0[64], sw1[64];
    int tid = threadIdx.x, w = tid >> 5, lane = tid & 31;
    size_t row = blockIdx.x;
    const float* q = query + row*EMB;

    if (tid < 64) {
        const float* ww = gW + tid*8;
        sw0[tid] = ww[0]+ww[1]+ww[2]+ww[3];
        sw1[tid] = ww[4]+ww[5]+ww[6]+ww[7];
    }
    float v0 = q[tid], v1 = q[tid + 384];
    xrow[tid] = v0; xrow[tid + 384] = v1;
    g_Xh[row*EMB + tid]       = __float2half_rn(v0);
    g_Xh[row*EMB + tid + 384] = __float2half_rn(v1);
    __syncthreads();

    float b0 = gb[0]+gb[1]+gb[2]+gb[3], b1 = gb[4]+gb[5]+gb[6]+gb[7];
    const float* xh = xrow + w*HD;
    float xa = xh[lane], xb = xh[lane + 32];
    float z0 = xa*sw0[lane] + xb*sw0[lane+32];
    float z1 = xa*sw1[lane] + xb*sw1[lane+32];
#pragma unroll
    for (int d = 16; d >= 1; d >>= 1) {
        z0 += __shfl_xor_sync(~0u, z0, d);
        z1 += __shfl_xor_sync(~0u, z1, d);
    }
    if (lane == 0) {
        z0 += b0; z1 += b1;
        float g0 = 1.f/(1.f+expf(-z0)), g1 = 1.f/(1.f+expf(-z1));
        int b = row >> 10, s = row & (SLEN-1);
        g_gate[(b*NH + w)*SLEN + s] = g0*(g1*gc[w]-1.f)+2.f;
    }
}

// ---- prep: transpose W ----
__global__ __launch_bounds__(256) void trans_w_kernel(
    const float* __restrict__ wq, const float* __restrict__ wk,
    const float* __restrict__ wv, const float* __restrict__ wo)
{
    __shared__ float t[32][33];
    int z = blockIdx.z;
    const float* W = (z==0)?wq:(z==1)?wk:(z==2)?wv:wo;
    int tx = threadIdx.x & 31, ty = threadIdx.x >> 5;
    int n0 = blockIdx.x*32, k0 = blockIdx.y*32;
#pragma unroll
    for (int r = 0; r < 4; r++)
        t[ty+r*8][tx] = W[(size_t)(k0+ty+r*8)*EMB + n0+tx];
    __syncthreads();
#pragma unroll
    for (int r = 0; r < 4; r++) {
        size_t o = (size_t)z*EMB*EMB + (size_t)(n0+ty+r*8)*EMB + k0+tx;
        g_WTh[o] = __float2half_rn(t[tx][ty+r*8]);
    }
}

// ==== fp16 1-term GEMM (R15): 256 thr, 8 warps 4(M)x2(N), warp 32x64,
// K-chunk 64, pitch 144B, 3-stage cp.async pipeline ====
#define GP 144
#define GTB (128*GP)
#define GSTAGE (2*GTB)
#define G_SMEM (3*GSTAGE)

__device__ __forceinline__ void cpa_tile64(const __half* __restrict__ g,
                                           int row0, int kc, uint32_t sdst, int tid) {
#pragma unroll
    for (int r = 0; r < 4; r++) {
        int u = tid + r*256, row = u >> 3, co = u & 7;
        cpa16(sdst + row*GP + co*16, g + (size_t)(row0+row)*EMB + kc + co*8);
    }
}

__device__ __forceinline__ void gemm_core(
    const __half* Ah, const __half* Bh,
    int bm, int bn, char* sm, float c[2][8][4])
{
    int tid = threadIdx.x, lane = tid & 31, wid = tid >> 5;
    int wm = wid & 3, wn = wid >> 2;
    uint32_t sb = smem_u32(sm);
    uint32_t aoff = (((lane>>3)&1)*8 + (lane&7))*GP + (lane>>4)*16;
    uint32_t boff = ((lane>>4)*8 + (lane&7))*GP + ((lane>>3)&1)*16;

    cpa_tile64(Ah, bm, 0, sb, tid);
    cpa_tile64(Bh, bn, 0, sb + GTB, tid);
    CP_COMMIT();
    cpa_tile64(Ah, bm, 64, sb + GSTAGE, tid);
    cpa_tile64(Bh, bn, 64, sb + GSTAGE + GTB, tid);
    CP_COMMIT();

    for (int cI = 0; cI < 12; cI++) {
        if (cI < 10) CP_WAIT1(); else CP_WAIT0();
        __syncthreads();
        if (cI < 10) {
            int stn = (cI + 2) % 3;
            uint32_t st = sb + stn*GSTAGE;
            int kc = (cI + 2)*64;
            cpa_tile64(Ah, bm, kc, st, tid);
            cpa_tile64(Bh, bn, kc, st + GTB, tid);
            CP_COMMIT();
        }
        uint32_t st = sb + (cI % 3)*GSTAGE;
        uint32_t aB = st + (wm*32)*GP + aoff;
        uint32_t bB = st + GTB + (wn*64)*GP + boff;
#pragma unroll
        for (int ks = 0; ks < 128; ks += 32) {
            uint32_t ah[2][4];
#pragma unroll
            for (int mi = 0; mi < 2; mi++)
                ldm4(ah[mi], aB + mi*16*GP + ks);
#pragma unroll
            for (int jf = 0; jf < 4; jf++) {
                uint32_t rb[4];
                ldm4(rb, bB + jf*16*GP + ks);
#pragma unroll
                for (int mi = 0; mi < 2; mi++) {
                    mma16816(c[mi][jf*2],   ah[mi], rb);
                    mma16816(c[mi][jf*2+1], ah[mi], rb+2);
                }
            }
        }
        __syncthreads();
    }
}

__global__ __launch_bounds__(256) void gemm_qkv_mma(
    const float* __restrict__ bq, const float* __restrict__ bk, const float* __restrict__ bv)
{
    extern __shared__ char sm[];
    int z = blockIdx.z, bm = blockIdx.y*128, bn = blockIdx.x*128;
    float c[2][8][4] = {};
    gemm_core(g_Xh, g_WTh + (size_t)z*EMB*EMB, bm, bn, sm, c);

    const float* bias = (z==0)?bq:(z==1)?bk:bv;
    __half* Out = (z==0)?g_Qh:(z==1)?g_Kh:g_Vh;
    float scale = (z==0)?0.125f:1.f;
    int lane = threadIdx.x & 31, wid = threadIdx.x >> 5;
    int wm = wid & 3, wn = wid >> 2;
    int g = lane >> 2, t2 = (lane & 3)*2;
#pragma unroll
    for (int mi = 0; mi < 2; mi++)
#pragma unroll
        for (int nf = 0; nf < 8; nf++) {
            int col = bn + wn*64 + nf*8 + t2;
            int h = col >> 6, d0 = col & 63;
            float bx = __ldg(&bias[col]), by = __ldg(&bias[col+1]);
#pragma unroll
            for (int rr = 0; rr < 2; rr++) {
                int m = bm + wm*32 + mi*16 + g + rr*8;
                int b = m >> 10, s = m & (SLEN-1);
                float vx = (c[mi][nf][rr*2+0] + bx)*scale;
                float vy = (c[mi][nf][rr*2+1] + by)*scale;
                __half2 hv;
                hv.x = __float2half_rn(vx); hv.y = __float2half_rn(vy);
                *(__half2*)(Out + ((size_t)(b*NH+h)*SLEN + s)*HD + d0) = hv;
            }
        }
}

__global__ __launch_bounds__(256) void gemm_out_mma(
    const float* __restrict__ bo, float* __restrict__ out)
{
    extern __shared__ char sm[];
    int bm = blockIdx.y*128, bn = blockIdx.x*128;
    float c[2][8][4] = {};
    gemm_core(g_AO, g_WTh + (size_t)3*EMB*EMB, bm, bn, sm, c);

    int lane = threadIdx.x & 31, wid = threadIdx.x >> 5;
    int wm = wid & 3, wn = wid >> 2;
    int g = lane >> 2, t2 = (lane & 3)*2;
#pragma unroll
    for (int mi = 0; mi < 2; mi++)
#pragma unroll
        for (int nf = 0; nf < 8; nf++) {
            int col = bn + wn*64 + nf*8 + t2;
            float bx = __ldg(&bo[col]), by = __ldg(&bo[col+1]);
#pragma unroll
            for (int rr = 0; rr < 2; rr++) {
                int m = bm + wm*32 + mi*16 + g + rr*8;
                float2 v;
                v.x = c[mi][nf][rr*2+0] + bx;
                v.y = c[mi][nf][rr*2+1] + by;
                *(float2*)(out + (size_t)m*EMB + col) = v;
            }
        }
}

// ==== fp16 flash attention: 128 thr, 4 warps of 32 q-rows ====
// rb via __ldg (no smem table) -> smem 55.8KB -> 4 blocks/SM.
#define AP 72
#define AS_KV 18432
#define KVST 18432
#define AS_GATE (18432 + 2*KVST)
#define AS_TOTAL (AS_GATE + 512)
#define SMAX 6.0f

__global__ __launch_bounds__(128) void attn_mma()
{
    extern __shared__ char smc[];
    __half* qs = (__half*)smc;
    float* gate_s = (float*)(smc + AS_GATE);

    int bh = blockIdx.x, qb = blockIdx.y, h = bh % NH;
    int tid = threadIdx.x, lane = tid & 31, w = tid >> 5;
    int g = lane >> 2, t2 = (lane & 3)*2;

    const __half* Qg = g_Qh + ((size_t)bh*SLEN + qb*128)*HD;
    const __half* Kg = g_Kh + (size_t)bh*SLEN*HD;
    const __half* Vg = g_Vh + (size_t)bh*SLEN*HD;
    const float* rbt = g_rbt + h*2048;

    {
        uint32_t kd = smem_u32(smc + AS_KV);
#pragma unroll
        for (int r = 0; r < 4; r++) {
            int u = tid + r*128, row = u >> 3, co = u & 7;
            cpa16(kd + row*144 + co*16,        Kg + (size_t)row*HD + co*8);
            cpa16(kd + 9216 + row*144 + co*16, Vg + (size_t)row*HD + co*8);
        }
        CP_COMMIT();
    }
#pragma unroll
    for (int r = 0; r < 8; r++) {
        int u = tid + r*128, row = u >> 3, co = u & 7;
        *(uint4*)(qs + row*AP + co*8) = *(const uint4*)(Qg + row*HD + co*8);
    }
    gate_s[tid] = g_gate[bh*SLEN + qb*128 + tid];
    __syncthreads();

    uint32_t aoff = (((lane>>3)&1)*8 + (lane&7))*144 + (lane>>4)*16;
    uint32_t boff = ((lane>>4)*8 + (lane&7))*144 + ((lane>>3)&1)*16;

    uint32_t qf[2][4][4];
    {
        uint32_t qB = smem_u32(qs) + w*32*144 + aoff;
#pragma unroll
        for (int mi = 0; mi < 2; mi++)
#pragma unroll
            for (int ks = 0; ks < 4; ks++)
                ldm4(qf[mi][ks], qB + mi*16*144 + ks*32);
    }
    float gq[2][2];
    int q0 = qb*128 + w*32 + g;
#pragma unroll
    for (int mi = 0; mi < 2; mi++) {
        gq[mi][0] = gate_s[w*32 + mi*16 + g];
        gq[mi][1] = gate_s[w*32 + mi*16 + g + 8];
    }

    float o[2][8][4] = {};
    float l[2][2] = {};

    for (int kb = 0; kb < 16; kb++) {
        CP_WAIT0();
        __syncthreads();
        if (kb < 15) {
            uint32_t kd = smem_u32(smc + AS_KV + ((kb+1)&1)*KVST);
#pragma unroll
            for (int r = 0; r < 4; r++) {
                int u = tid + r*128, row = u >> 3, co = u & 7;
                size_t go = (size_t)((kb+1)*64 + row)*HD + co*8;
                cpa16(kd + row*144 + co*16,        Kg + go);
                cpa16(kd + 9216 + row*144 + co*16, Vg + go);
            }
            CP_COMMIT();
        }
        uint32_t kB = smem_u32(smc + AS_KV + (kb&1)*KVST) + boff;
        uint32_t vB = smem_u32(smc + AS_KV + (kb&1)*KVST + 9216) + aoff;

        float s[2][8][4] = {};
#pragma unroll
        for (int ks = 0; ks < 4; ks++)
#pragma unroll
            for (int nb = 0; nb < 4; nb++) {
                uint32_t rk[4];
                ldm4(rk, kB + nb*16*144 + ks*32);
#pragma unroll
                for (int mi = 0; mi < 2; mi++) {
                    mma16816(s[mi][nb*2],   qf[mi][ks], rk);
                    mma16816(s[mi][nb*2+1], qf[mi][ks], rk+2);
                }
            }

        int cbase = kb*64 + t2 + 1023;
#pragma unroll
        for (int mi = 0; mi < 2; mi++) {
            const float* r0p = rbt + (cbase - (q0 + mi*16));
            const float* r1p = r0p - 8;
#pragma unroll
            for (int nf = 0; nf < 8; nf++) {
                int d = nf*8;
                s[mi][nf][0] = fexp(fmaf(gq[mi][0], __ldg(r0p + d),     s[mi][nf][0]) - SMAX);
                s[mi][nf][1] = fexp(fmaf(gq[mi][0], __ldg(r0p + d + 1), s[mi][nf][1]) - SMAX);
                s[mi][nf][2] = fexp(fmaf(gq[mi][1], __ldg(r1p + d),     s[mi][nf][2]) - SMAX);
                s[mi][nf][3] = fexp(fmaf(gq[mi][1], __ldg(r1p + d + 1), s[mi][nf][3]) - SMAX);
            }
        }

#pragma unroll
        for (int ks = 0; ks < 4; ks++) {
            uint32_t pah[2][4];
#pragma unroll
            for (int mi = 0; mi < 2; mi++) {
                float* p0 = s[mi][2*ks];
                float* p1 = s[mi][2*ks+1];
                pah[mi][0] = packh2(p0[1], p0[0]);
                pah[mi][1] = packh2(p0[3], p0[2]);
                pah[mi][2] = packh2(p1[1], p1[0]);
                pah[mi][3] = packh2(p1[3], p1[2]);
                float2 a0 = __half22float2(*(__half2*)&pah[mi][0]);
                float2 a1 = __half22float2(*(__half2*)&pah[mi][1]);
                float2 a2 = __half22float2(*(__half2*)&pah[mi][2]);
                float2 a3 = __half22float2(*(__half2*)&pah[mi][3]);
                l[mi][0] += (a0.x + a0.y) + (a2.x + a2.y);
                l[mi][1] += (a1.x + a1.y) + (a3.x + a3.y);
            }
#pragma unroll
            for (int db = 0; db < 4; db++) {
                uint32_t rv[4];
                ldm4t(rv, vB + ks*16*144 + db*32);
#pragma unroll
                for (int mi = 0; mi < 2; mi++) {
                    mma16816(o[mi][db*2],   pah[mi], rv);
                    mma16816(o[mi][db*2+1], pah[mi], rv+2);
                }
            }
        }
    }

    int b = bh / NH;
#pragma unroll
    for (int mi = 0; mi < 2; mi++) {
        float l0 = l[mi][0], l1 = l[mi][1];
        l0 += __shfl_xor_sync(~0u, l0, 1); l0 += __shfl_xor_sync(~0u, l0, 2);
        l1 += __shfl_xor_sync(~0u, l1, 1); l1 += __shfl_xor_sync(~0u, l1, 2);
        float inv0 = 1.f/l0, inv1 = 1.f/l1;
        int r0 = q0 + mi*16;
        size_t base0 = ((size_t)(b*SLEN) + r0)*EMB + h*HD;
        size_t base1 = base0 + (size_t)8*EMB;
#pragma unroll
        for (int nf = 0; nf < 8; nf++) {
            int d = nf*8 + t2;
            __half2 hv;
            hv.x = __float2half_rn(o[mi][nf][0]*inv0);
            hv.y = __float2half_rn(o[mi][nf][1]*inv0);
            *(__half2*)(g_AO + base0 + d) = hv;
            hv.x = __float2half_rn(o[mi][nf][2]*inv1);
            hv.y = __float2half_rn(o[mi][nf][3]*inv1);
            *(__half2*)(g_AO + base1 + d) = hv;
        }
    }
}

// ---- launcher ----
extern "C" void kernel_launch(void* const* d_in, const int* in_sizes, int n_in,
                              void* d_out, int out_size)
{
    const float* query = (const float*)d_in[0];
    const float *Wq=(const float*)d_in[1], *bq=(const float*)d_in[2];
    const float *Wk=(const float*)d_in[3], *bk=(const float*)d_in[4];
    const float *Wv=(const float*)d_in[5], *bv=(const float*)d_in[6];
    const float *Wo=(const float*)d_in[7], *bo=(const float*)d_in[8];
    const float *rel=(const float*)d_in[9];
    const float *gruW=(const float*)d_in[10], *grub=(const float*)d_in[11], *gruc=(const float*)d_in[12];

    cudaFuncSetAttribute(attn_mma, cudaFuncAttributeMaxDynamicSharedMemorySize, AS_TOTAL);
    cudaFuncSetAttribute(gemm_qkv_mma, cudaFuncAttributeMaxDynamicSharedMemorySize, G_SMEM);
    cudaFuncSetAttribute(gemm_out_mma, cudaFuncAttributeMaxDynamicSharedMemorySize, G_SMEM);

    rb_kernel<<<dim3(8, NH), 256>>>(rel);
    prep_x_kernel<<<MROWS, 384>>>(query, gruW, grub, gruc);
    trans_w_kernel<<<dim3(EMB/32, EMB/32, 4), 256>>>(Wq, Wk, Wv, Wo);
    gemm_qkv_mma<<<dim3(EMB/128, MROWS/128, 3), 256, G_SMEM>>>(bq, bk, bv);
    attn_mma<<<dim3(BATCH*NH, SLEN/128), 128, AS_TOTAL>>>();
    gemm_out_mma<<<dim3(EMB/128, MROWS/128), 256, G_SMEM>>>(bo, (float*)d_out);
}

// round 17
// speedup vs baseline: 1.0549x; 1.0549x over previous
#include <cuda_runtime.h>
#include <cuda_fp16.h>
#include <cstdint>
#include <math.h>

#define BATCH 8
#define SLEN 1024
#define EMB 768
#define NH 12
#define HD 64
#define MROWS (BATCH*SLEN)

__device__ float g_gate[BATCH*NH*SLEN];
__device__ float g_rbt[NH*2048];
__device__ __half g_Xh[MROWS*EMB];
__device__ __half g_AO[MROWS*EMB];
__device__ __half g_WTh[4*EMB*EMB];
__device__ __half g_Qh[BATCH*NH*SLEN*HD];
__device__ __half g_Kh[BATCH*NH*SLEN*HD];
__device__ __half g_Vh[BATCH*NH*SLEN*HD];

__device__ __forceinline__ uint32_t smem_u32(const void* p) {
    uint32_t a;
    asm("{.reg .u64 t; cvta.to.shared.u64 t,%1; cvt.u32.u64 %0,t;}" : "=r"(a) : "l"(p));
    return a;
}
__device__ __forceinline__ void ldm4(uint32_t* r, uint32_t addr) {
    asm volatile("ldmatrix.sync.aligned.m8n8.x4.shared.b16 {%0,%1,%2,%3}, [%4];"
        : "=r"(r[0]),"=r"(r[1]),"=r"(r[2]),"=r"(r[3]) : "r"(addr));
}
__device__ __forceinline__ void ldm4t(uint32_t* r, uint32_t addr) {
    asm volatile("ldmatrix.sync.aligned.m8n8.x4.trans.shared.b16 {%0,%1,%2,%3}, [%4];"
        : "=r"(r[0]),"=r"(r[1]),"=r"(r[2]),"=r"(r[3]) : "r"(addr));
}
__device__ __forceinline__ void mma16816(float* c, const uint32_t* a, const uint32_t* b) {
    asm volatile("mma.sync.aligned.m16n8k16.row.col.f32.f16.f16.f32 "
        "{%0,%1,%2,%3}, {%4,%5,%6,%7}, {%8,%9}, {%0,%1,%2,%3};"
        : "+f"(c[0]),"+f"(c[1]),"+f"(c[2]),"+f"(c[3])
        : "r"(a[0]),"r"(a[1]),"r"(a[2]),"r"(a[3]), "r"(b[0]),"r"(b[1]));
}
__device__ __forceinline__ uint32_t packh2(float hi, float lo) {
    uint32_t r;
    asm("cvt.rn.f16x2.f32 %0, %1, %2;" : "=r"(r) : "f"(hi), "f"(lo));
    return r;
}
__device__ __forceinline__ void cpa16(uint32_t saddr, const void* g) {
    asm volatile("cp.async.cg.shared.global [%0], [%1], 16;" :: "r"(saddr), "l"(g));
}
#define CP_COMMIT() asm volatile("cp.async.commit_group;" ::: "memory")
#define CP_WAIT0()  asm volatile("cp.async.wait_group 0;" ::: "memory")
#define CP_WAIT1()  asm volatile("cp.async.wait_group 1;" ::: "memory")

// e^x for x in [-40, 0], FMA-pipe only
__device__ __forceinline__ float fexp(float x) {
    float y = x * 1.4426950408889634f;
    float t = y + 12582912.f;
    int  i = __float_as_int(t) << 23;
    float f = y - (t - 12582912.f);
    float p = 0.0013333558f;
    p = fmaf(p, f, 0.0096181291f);
    p = fmaf(p, f, 0.0555041087f);
    p = fmaf(p, f, 0.2402265069f);
    p = fmaf(p, f, 0.6931471806f);
    p = fmaf(p, f, 1.0f);
    return __int_as_float(__float_as_int(p) + i);
}

// ==== fused prep: prep_x (blocks [0,8192)) + trans_w ([8192,10496)) + rb ([10496,10560)) ====
#define PREP_X_BLKS 8192
#define TRANS_BLKS  2304
#define RB_BLKS     64

__global__ __launch_bounds__(384) void prep_all_kernel(
    const float* __restrict__ query, const float* __restrict__ gW,
    const float* __restrict__ gb, const float* __restrict__ gc,
    const float* __restrict__ wq, const float* __restrict__ wk,
    const float* __restrict__ wv, const float* __restrict__ wo,
    const float* __restrict__ rel_embed)
{
    int bid = blockIdx.x;
    int tid = threadIdx.x;

    if (bid < PREP_X_BLKS) {
        // ---- X -> fp16 + gate ----
        __shared__ float xrow[EMB];
        __shared__ float sw0[64], sw1[64];
        int w = tid >> 5, lane = tid & 31;
        size_t row = bid;
        const float* q = query + row*EMB;
        if (tid < 64) {
            const float* ww = gW + tid*8;
            sw0[tid] = ww[0]+ww[1]+ww[2]+ww[3];
            sw1[tid] = ww[4]+ww[5]+ww[6]+ww[7];
        }
        float v0 = q[tid], v1 = q[tid + 384];
        xrow[tid] = v0; xrow[tid + 384] = v1;
        g_Xh[row*EMB + tid]       = __float2half_rn(v0);
        g_Xh[row*EMB + tid + 384] = __float2half_rn(v1);
        __syncthreads();
        float b0 = gb[0]+gb[1]+gb[2]+gb[3], b1 = gb[4]+gb[5]+gb[6]+gb[7];
        const float* xh = xrow + w*HD;
        float xa = xh[lane], xb = xh[lane + 32];
        float z0 = xa*sw0[lane] + xb*sw0[lane+32];
        float z1 = xa*sw1[lane] + xb*sw1[lane+32];
#pragma unroll
        for (int d = 16; d >= 1; d >>= 1) {
            z0 += __shfl_xor_sync(~0u, z0, d);
            z1 += __shfl_xor_sync(~0u, z1, d);
        }
        if (lane == 0) {
            z0 += b0; z1 += b1;
            float g0 = 1.f/(1.f+expf(-z0)), g1 = 1.f/(1.f+expf(-z1));
            int b = (int)(row >> 10), s = (int)(row & (SLEN-1));
            g_gate[(b*NH + w)*SLEN + s] = g0*(g1*gc[w]-1.f)+2.f;
        }
    } else if (bid < PREP_X_BLKS + TRANS_BLKS) {
        // ---- transpose W (uses first 256 threads) ----
        __shared__ float t[32][33];
        int b2 = bid - PREP_X_BLKS;
        int z = b2 / 576, rem = b2 % 576;
        int n0 = (rem % 24)*32, k0 = (rem / 24)*32;
        const float* W = (z==0)?wq:(z==1)?wk:(z==2)?wv:wo;
        int tx = tid & 31, ty = tid >> 5;
        if (tid < 256) {
#pragma unroll
            for (int r = 0; r < 4; r++)
                t[ty+r*8][tx] = W[(size_t)(k0+ty+r*8)*EMB + n0+tx];
        }
        __syncthreads();
        if (tid < 256) {
#pragma unroll
            for (int r = 0; r < 4; r++) {
                size_t o = (size_t)z*EMB*EMB + (size_t)(n0+ty+r*8)*EMB + k0+tx;
                g_WTh[o] = __float2half_rn(t[tx][ty+r*8]);
            }
        }
    } else {
        // ---- rel-bias table ----
        int idx = (bid - PREP_X_BLKS - TRANS_BLKS)*384 + tid;   // 0..24575
        int h = idx >> 11, pos = idx & 2047;
        int rp = pos - 1023;
        int base = (rp > 0) ? 16 : 0, a = abs(rp), add;
        if(a<8)add=a; else if(a<12)add=8; else if(a<16)add=9; else if(a<23)add=10;
        else if(a<32)add=11; else if(a<46)add=12; else if(a<64)add=13; else if(a<91)add=14; else add=15;
        float v = (pos < 2047) ? rel_embed[(base+add)*NH + h] : 0.f;
        g_rbt[h*2048 + pos] = v;
    }
}

// ==== fp16 1-term GEMM (R15): 256 thr, 8 warps 4(M)x2(N), warp 32x64,
// K-chunk 64, pitch 144B, 3-stage cp.async pipeline ====
#define GP 144
#define GTB (128*GP)
#define GSTAGE (2*GTB)
#define G_SMEM (3*GSTAGE)

__device__ __forceinline__ void cpa_tile64(const __half* __restrict__ g,
                                           int row0, int kc, uint32_t sdst, int tid) {
#pragma unroll
    for (int r = 0; r < 4; r++) {
        int u = tid + r*256, row = u >> 3, co = u & 7;
        cpa16(sdst + row*GP + co*16, g + (size_t)(row0+row)*EMB + kc + co*8);
    }
}

__device__ __forceinline__ void gemm_core(
    const __half* Ah, const __half* Bh,
    int bm, int bn, char* sm, float c[2][8][4])
{
    int tid = threadIdx.x, lane = tid & 31, wid = tid >> 5;
    int wm = wid & 3, wn = wid >> 2;
    uint32_t sb = smem_u32(sm);
    uint32_t aoff = (((lane>>3)&1)*8 + (lane&7))*GP + (lane>>4)*16;
    uint32_t boff = ((lane>>4)*8 + (lane&7))*GP + ((lane>>3)&1)*16;

    cpa_tile64(Ah, bm, 0, sb, tid);
    cpa_tile64(Bh, bn, 0, sb + GTB, tid);
    CP_COMMIT();
    cpa_tile64(Ah, bm, 64, sb + GSTAGE, tid);
    cpa_tile64(Bh, bn, 64, sb + GSTAGE + GTB, tid);
    CP_COMMIT();

    for (int cI = 0; cI < 12; cI++) {
        if (cI < 10) CP_WAIT1(); else CP_WAIT0();
        __syncthreads();
        if (cI < 10) {
            int stn = (cI + 2) % 3;
            uint32_t st = sb + stn*GSTAGE;
            int kc = (cI + 2)*64;
            cpa_tile64(Ah, bm, kc, st, tid);
            cpa_tile64(Bh, bn, kc, st + GTB, tid);
            CP_COMMIT();
        }
        uint32_t st = sb + (cI % 3)*GSTAGE;
        uint32_t aB = st + (wm*32)*GP + aoff;
        uint32_t bB = st + GTB + (wn*64)*GP + boff;
#pragma unroll
        for (int ks = 0; ks < 128; ks += 32) {
            uint32_t ah[2][4];
#pragma unroll
            for (int mi = 0; mi < 2; mi++)
                ldm4(ah[mi], aB + mi*16*GP + ks);
#pragma unroll
            for (int jf = 0; jf < 4; jf++) {
                uint32_t rb[4];
                ldm4(rb, bB + jf*16*GP + ks);
#pragma unroll
                for (int mi = 0; mi < 2; mi++) {
                    mma16816(c[mi][jf*2],   ah[mi], rb);
                    mma16816(c[mi][jf*2+1], ah[mi], rb+2);
                }
            }
        }
        __syncthreads();
    }
}

__global__ __launch_bounds__(256) void gemm_qkv_mma(
    const float* __restrict__ bq, const float* __restrict__ bk, const float* __restrict__ bv)
{
    extern __shared__ char sm[];
    int z = blockIdx.z, bm = blockIdx.y*128, bn = blockIdx.x*128;
    float c[2][8][4] = {};
    gemm_core(g_Xh, g_WTh + (size_t)z*EMB*EMB, bm, bn, sm, c);

    const float* bias = (z==0)?bq:(z==1)?bk:bv;
    __half* Out = (z==0)?g_Qh:(z==1)?g_Kh:g_Vh;
    float scale = (z==0)?0.125f:1.f;
    int lane = threadIdx.x & 31, wid = threadIdx.x >> 5;
    int wm = wid & 3, wn = wid >> 2;
    int g = lane >> 2, t2 = (lane & 3)*2;
#pragma unroll
    for (int mi = 0; mi < 2; mi++)
#pragma unroll
        for (int nf = 0; nf < 8; nf++) {
            int col = bn + wn*64 + nf*8 + t2;
            int h = col >> 6, d0 = col & 63;
            float bx = __ldg(&bias[col]), by = __ldg(&bias[col+1]);
#pragma unroll
            for (int rr = 0; rr < 2; rr++) {
                int m = bm + wm*32 + mi*16 + g + rr*8;
                int b = m >> 10, s = m & (SLEN-1);
                float vx = (c[mi][nf][rr*2+0] + bx)*scale;
                float vy = (c[mi][nf][rr*2+1] + by)*scale;
                __half2 hv;
                hv.x = __float2half_rn(vx); hv.y = __float2half_rn(vy);
                *(__half2*)(Out + ((size_t)(b*NH+h)*SLEN + s)*HD + d0) = hv;
            }
        }
}

__global__ __launch_bounds__(256) void gemm_out_mma(
    const float* __restrict__ bo, float* __restrict__ out)
{
    extern __shared__ char sm[];
    int bm = blockIdx.y*128, bn = blockIdx.x*128;
    float c[2][8][4] = {};
    gemm_core(g_AO, g_WTh + (size_t)3*EMB*EMB, bm, bn, sm, c);

    int lane = threadIdx.x & 31, wid = threadIdx.x >> 5;
    int wm = wid & 3, wn = wid >> 2;
    int g = lane >> 2, t2 = (lane & 3)*2;
#pragma unroll
    for (int mi = 0; mi < 2; mi++)
#pragma unroll
        for (int nf = 0; nf < 8; nf++) {
            int col = bn + wn*64 + nf*8 + t2;
            float bx = __ldg(&bo[col]), by = __ldg(&bo[col+1]);
#pragma unroll
            for (int rr = 0; rr < 2; rr++) {
                int m = bm + wm*32 + mi*16 + g + rr*8;
                float2 v;
                v.x = c[mi][nf][rr*2+0] + bx;
                v.y = c[mi][nf][rr*2+1] + by;
                *(float2*)(out + (size_t)m*EMB + col) = v;
            }
        }
}

// ==== fp16 flash attention (R15): 128 thr, 4 warps of 32 q-rows, smem rb ====
#define AP 72
#define AS_KV 18432
#define KVST 18432
#define AS_GATE (18432 + 2*KVST)
#define AS_RB   (AS_GATE + 512)
#define AS_TOTAL (AS_RB + 8192)
#define SMAX 6.0f

__global__ __launch_bounds__(128) void attn_mma()
{
    extern __shared__ char smc[];
    __half* qs = (__half*)smc;
    float* gate_s = (float*)(smc + AS_GATE);
    float* rb_s   = (float*)(smc + AS_RB);

    int bh = blockIdx.x, qb = blockIdx.y, h = bh % NH;
    int tid = threadIdx.x, lane = tid & 31, w = tid >> 5;
    int g = lane >> 2, t2 = (lane & 3)*2;

    const __half* Qg = g_Qh + ((size_t)bh*SLEN + qb*128)*HD;
    const __half* Kg = g_Kh + (size_t)bh*SLEN*HD;
    const __half* Vg = g_Vh + (size_t)bh*SLEN*HD;

    {
        uint32_t kd = smem_u32(smc + AS_KV);
#pragma unroll
        for (int r = 0; r < 4; r++) {
            int u = tid + r*128, row = u >> 3, co = u & 7;
            cpa16(kd + row*144 + co*16,        Kg + (size_t)row*HD + co*8);
            cpa16(kd + 9216 + row*144 + co*16, Vg + (size_t)row*HD + co*8);
        }
        CP_COMMIT();
    }
#pragma unroll
    for (int r = 0; r < 8; r++) {
        int u = tid + r*128, row = u >> 3, co = u & 7;
        *(uint4*)(qs + row*AP + co*8) = *(const uint4*)(Qg + row*HD + co*8);
    }
    gate_s[tid] = g_gate[bh*SLEN + qb*128 + tid];
#pragma unroll
    for (int r = 0; r < 16; r++)
        rb_s[tid + r*128] = g_rbt[h*2048 + tid + r*128];
    __syncthreads();

    uint32_t aoff = (((lane>>3)&1)*8 + (lane&7))*144 + (lane>>4)*16;
    uint32_t boff = ((lane>>4)*8 + (lane&7))*144 + ((lane>>3)&1)*16;

    uint32_t qf[2][4][4];
    {
        uint32_t qB = smem_u32(qs) + w*32*144 + aoff;
#pragma unroll
        for (int mi = 0; mi < 2; mi++)
#pragma unroll
            for (int ks = 0; ks < 4; ks++)
                ldm4(qf[mi][ks], qB + mi*16*144 + ks*32);
    }
    float gq[2][2];
    int q0 = qb*128 + w*32 + g;
#pragma unroll
    for (int mi = 0; mi < 2; mi++) {
        gq[mi][0] = gate_s[w*32 + mi*16 + g];
        gq[mi][1] = gate_s[w*32 + mi*16 + g + 8];
    }

    float o[2][8][4] = {};
    float l[2][2] = {};

    for (int kb = 0; kb < 16; kb++) {
        CP_WAIT0();
        __syncthreads();
        if (kb < 15) {
            uint32_t kd = smem_u32(smc + AS_KV + ((kb+1)&1)*KVST);
#pragma unroll
            for (int r = 0; r < 4; r++) {
                int u = tid + r*128, row = u >> 3, co = u & 7;
                size_t go = (size_t)((kb+1)*64 + row)*HD + co*8;
                cpa16(kd + row*144 + co*16,        Kg + go);
                cpa16(kd + 9216 + row*144 + co*16, Vg + go);
            }
            CP_COMMIT();
        }
        uint32_t kB = smem_u32(smc + AS_KV + (kb&1)*KVST) + boff;
        uint32_t vB = smem_u32(smc + AS_KV + (kb&1)*KVST + 9216) + aoff;

        float s[2][8][4] = {};
#pragma unroll
        for (int ks = 0; ks < 4; ks++)
#pragma unroll
            for (int nb = 0; nb < 4; nb++) {
                uint32_t rk[4];
                ldm4(rk, kB + nb*16*144 + ks*32);
#pragma unroll
                for (int mi = 0; mi < 2; mi++) {
                    mma16816(s[mi][nb*2],   qf[mi][ks], rk);
                    mma16816(s[mi][nb*2+1], qf[mi][ks], rk+2);
                }
            }

        int cbase = kb*64 + t2 + 1023;
#pragma unroll
        for (int mi = 0; mi < 2; mi++) {
            int i0 = cbase - (q0 + mi*16);
            int i1 = i0 - 8;
#pragma unroll
            for (int nf = 0; nf < 8; nf++) {
                int d = nf*8;
                s[mi][nf][0] = fexp(fmaf(gq[mi][0], rb_s[i0 + d],     s[mi][nf][0]) - SMAX);
                s[mi][nf][1] = fexp(fmaf(gq[mi][0], rb_s[i0 + d + 1], s[mi][nf][1]) - SMAX);
                s[mi][nf][2] = fexp(fmaf(gq[mi][1], rb_s[i1 + d],     s[mi][nf][2]) - SMAX);
                s[mi][nf][3] = fexp(fmaf(gq[mi][1], rb_s[i1 + d + 1], s[mi][nf][3]) - SMAX);
            }
        }

#pragma unroll
        for (int ks = 0; ks < 4; ks++) {
            uint32_t pah[2][4];
#pragma unroll
            for (int mi = 0; mi < 2; mi++) {
                float* p0 = s[mi][2*ks];
                float* p1 = s[mi][2*ks+1];
                pah[mi][0] = packh2(p0[1], p0[0]);
                pah[mi][1] = packh2(p0[3], p0[2]);
                pah[mi][2] = packh2(p1[1], p1[0]);
                pah[mi][3] = packh2(p1[3], p1[2]);
                float2 a0 = __half22float2(*(__half2*)&pah[mi][0]);
                float2 a1 = __half22float2(*(__half2*)&pah[mi][1]);
                float2 a2 = __half22float2(*(__half2*)&pah[mi][2]);
                float2 a3 = __half22float2(*(__half2*)&pah[mi][3]);
                l[mi][0] += (a0.x + a0.y) + (a2.x + a2.y);
                l[mi][1] += (a1.x + a1.y) + (a3.x + a3.y);
            }
#pragma unroll
            for (int db = 0; db < 4; db++) {
                uint32_t rv[4];
                ldm4t(rv, vB + ks*16*144 + db*32);
#pragma unroll
                for (int mi = 0; mi < 2; mi++) {
                    mma16816(o[mi][db*2],   pah[mi], rv);
                    mma16816(o[mi][db*2+1], pah[mi], rv+2);
                }
            }
        }
    }

    int b = bh / NH;
#pragma unroll
    for (int mi = 0; mi < 2; mi++) {
        float l0 = l[mi][0], l1 = l[mi][1];
        l0 += __shfl_xor_sync(~0u, l0, 1); l0 += __shfl_xor_sync(~0u, l0, 2);
        l1 += __shfl_xor_sync(~0u, l1, 1); l1 += __shfl_xor_sync(~0u, l1, 2);
        float inv0 = 1.f/l0, inv1 = 1.f/l1;
        int r0 = q0 + mi*16;
        size_t base0 = ((size_t)(b*SLEN) + r0)*EMB + h*HD;
        size_t base1 = base0 + (size_t)8*EMB;
#pragma unroll
        for (int nf = 0; nf < 8; nf++) {
            int d = nf*8 + t2;
            __half2 hv;
            hv.x = __float2half_rn(o[mi][nf][0]*inv0);
            hv.y = __float2half_rn(o[mi][nf][1]*inv0);
            *(__half2*)(g_AO + base0 + d) = hv;
            hv.x = __float2half_rn(o[mi][nf][2]*inv1);
            hv.y = __float2half_rn(o[mi][nf][3]*inv1);
            *(__half2*)(g_AO + base1 + d) = hv;
        }
    }
}

// ---- launcher ----
extern "C" void kernel_launch(void* const* d_in, const int* in_sizes, int n_in,
                              void* d_out, int out_size)
{
    const float* query = (const float*)d_in[0];
    const float *Wq=(const float*)d_in[1], *bq=(const float*)d_in[2];
    const float *Wk=(const float*)d_in[3], *bk=(const float*)d_in[4];
    const float *Wv=(const float*)d_in[5], *bv=(const float*)d_in[6];
    const float *Wo=(const float*)d_in[7], *bo=(const float*)d_in[8];
    const float *rel=(const float*)d_in[9];
    const float *gruW=(const float*)d_in[10], *grub=(const float*)d_in[11], *gruc=(const float*)d_in[12];

    cudaFuncSetAttribute(attn_mma, cudaFuncAttributeMaxDynamicSharedMemorySize, AS_TOTAL);
    cudaFuncSetAttribute(gemm_qkv_mma, cudaFuncAttributeMaxDynamicSharedMemorySize, G_SMEM);
    cudaFuncSetAttribute(gemm_out_mma, cudaFuncAttributeMaxDynamicSharedMemorySize, G_SMEM);

    prep_all_kernel<<<PREP_X_BLKS + TRANS_BLKS + RB_BLKS, 384>>>(
        query, gruW, grub, gruc, Wq, Wk, Wv, Wo, rel);
    gemm_qkv_mma<<<dim3(EMB/128, MROWS/128, 3), 256, G_SMEM>>>(bq, bk, bv);
    attn_mma<<<dim3(BATCH*NH, SLEN/128), 128, AS_TOTAL>>>();
    gemm_out_mma<<<dim3(EMB/128, MROWS/128), 256, G_SMEM>>>(bo, (float*)d_out);
}